// round 3
// baseline (speedup 1.0000x reference)
#include <cuda_runtime.h>
#include <cstdint>

// Problem dims (fixed by setup_inputs)
#define BB 512
#define TT 512
#define SS 64
#define HH 128
#define G3 384
#define AA 8

// Scratch: device globals (allocation inside kernel_launch is forbidden)
__device__ float g_z[(size_t)BB * TT * HH];   // 134 MB: relu(LN(x@Wf^T+bf))
__device__ float g_gx[(size_t)BB * TT * G3];  // 402 MB: z@Wih^T+bih, layout (T,B,3H)

typedef unsigned long long ull;

__device__ __forceinline__ ull pk2(float lo, float hi) {
    ull r; asm("mov.b64 %0, {%1,%2};" : "=l"(r) : "f"(lo), "f"(hi)); return r;
}
__device__ __forceinline__ float2 upk2(ull v) {
    float2 f; asm("mov.b64 {%0,%1}, %2;" : "=f"(f.x), "=f"(f.y) : "l"(v)); return f;
}
// packed fp32x2 FMA (SASS FFMA2): 2x fp32 throughput vs scalar FFMA
__device__ __forceinline__ ull fma2(ull a, ull b, ull c) {
    ull d; asm("fma.rn.f32x2 %0, %1, %2, %3;" : "=l"(d) : "l"(a), "l"(b), "l"(c)); return d;
}
__device__ __forceinline__ float sigmf(float x) { return 1.0f / (1.0f + __expf(-x)); }

// ============================================================================
// Kernel A1: z = relu(LN(x @ Wf^T + bf))   (persistent, 4 CTAs/SM)
// 256 threads, 16 rows/tile. Stage1: thread-per-h (2 groups x 128), f32x2 over
// row pairs. Stage2: warp-per-row LN via shuffles.
// ============================================================================
__global__ void __launch_bounds__(256) k_feat(
    const float* __restrict__ x, const float* __restrict__ Wf,
    const float* __restrict__ bf, const float* __restrict__ gf,
    const float* __restrict__ betaf)
{
    extern __shared__ float sm[];
    float* Wt  = sm;           // [64][128] transposed W_feat
    float* xs  = Wt + 8192;    // [64][16] x tile, row-interleaved
    float* fs  = xs + 1024;    // [16][128] pre-LN
    float* bfs = fs + 2048;    // 128
    float* gfs = bfs + 128;    // 128
    float* bes = gfs + 128;    // 128

    const int tid = threadIdx.x;
    for (int i = tid; i < 8192; i += 256) {            // Wf[h*64+s] -> Wt[s*128+h]
        int h = i >> 6, s = i & 63;
        Wt[s * 128 + h] = Wf[i];
    }
    for (int i = tid; i < 128; i += 256) { bfs[i] = bf[i]; gfs[i] = gf[i]; bes[i] = betaf[i]; }
    __syncthreads();

    const int gg = tid >> 7, h = tid & 127;
    const int lane = tid & 31, wid = tid >> 5;

    for (int tile = blockIdx.x; tile < (BB * TT / 16); tile += gridDim.x) {
        const int row0 = tile * 16;
        for (int i = tid; i < 1024; i += 256) {        // coalesced x load
            int r = i >> 6, s = i & 63;
            xs[s * 16 + r] = x[(size_t)(row0 + r) * 64 + s];
        }
        __syncthreads();

        ull acc[4];
#pragma unroll
        for (int p = 0; p < 4; ++p) acc[p] = 0ULL;
#pragma unroll 8
        for (int s = 0; s < 64; ++s) {
            float w = Wt[s * 128 + h];
            ull w2 = pk2(w, w);
            ulonglong2 xa = *(const ulonglong2*)&xs[s * 16 + gg * 8];
            ulonglong2 xb = *(const ulonglong2*)&xs[s * 16 + gg * 8 + 4];
            acc[0] = fma2(w2, xa.x, acc[0]);
            acc[1] = fma2(w2, xa.y, acc[1]);
            acc[2] = fma2(w2, xb.x, acc[2]);
            acc[3] = fma2(w2, xb.y, acc[3]);
        }
        const float bbv = bfs[h];
#pragma unroll
        for (int p = 0; p < 4; ++p) {
            float2 f = upk2(acc[p]);
            fs[(gg * 8 + 2 * p) * 128 + h]     = f.x + bbv;
            fs[(gg * 8 + 2 * p + 1) * 128 + h] = f.y + bbv;
        }
        __syncthreads();

        // LN + relu, warp `wid` handles rows 2*wid, 2*wid+1
#pragma unroll
        for (int rr = 0; rr < 2; ++rr) {
            const int row = wid * 2 + rr;
            float v[4], s1 = 0.f, s2 = 0.f;
#pragma unroll
            for (int q = 0; q < 4; ++q) {
                v[q] = fs[row * 128 + lane + 32 * q];
                s1 += v[q]; s2 += v[q] * v[q];
            }
#pragma unroll
            for (int o = 16; o > 0; o >>= 1) {
                s1 += __shfl_xor_sync(0xffffffffu, s1, o);
                s2 += __shfl_xor_sync(0xffffffffu, s2, o);
            }
            const float mu = s1 * (1.f / 128.f);
            const float rstd = rsqrtf(s2 * (1.f / 128.f) - mu * mu + 1e-5f);
#pragma unroll
            for (int q = 0; q < 4; ++q) {
                int k = lane + 32 * q;
                float zv = (v[q] - mu) * rstd * gfs[k] + bes[k];
                g_z[(size_t)(row0 + row) * 128 + k] = fmaxf(zv, 0.f);
            }
        }
        __syncthreads();
    }
}

// ============================================================================
// Kernel A2: gx = z @ Wih^T + bih, stored as (T, B, 3H).
// 384 threads (thread-per-gate), W_ih transposed+chunked in SMEM (192KB,
// 1 CTA/SM, persistent grid=148). 16 rows/tile, f32x2 over row pairs.
// ============================================================================
__global__ void __launch_bounds__(384) k_gx(
    const float* __restrict__ Wih, const float* __restrict__ bih)
{
    extern __shared__ float sm[];
    float* Wc = sm;            // 49152: Wc[(h>>2)*1536 + g*4 + (h&3)] = Wih[g*128+h]
    float* zs = Wc + 49152;    // [128][16]
    float* bs = zs + 2048;     // 384

    const int tid = threadIdx.x, g = tid;
    for (int i = tid; i < 49152; i += 384) {
        int gg2 = i >> 7, k = i & 127;
        Wc[(k >> 2) * 1536 + gg2 * 4 + (k & 3)] = Wih[i];
    }
    bs[tid] = bih[tid];
    __syncthreads();

    const float bbv = bs[g];
    for (int tile = blockIdx.x; tile < (BB * TT / 16); tile += gridDim.x) {
        const int row0 = tile * 16;
        for (int i = tid; i < 2048; i += 384) {
            int r = i >> 7, k = i & 127;
            zs[k * 16 + r] = g_z[(size_t)(row0 + r) * 128 + k];
        }
        __syncthreads();

        ull acc[8];
#pragma unroll
        for (int p = 0; p < 8; ++p) acc[p] = pk2(bbv, bbv) ;
        // bias counted 8x? No: each acc[p] is a distinct row pair -> bias once per row. OK.
#pragma unroll 4
        for (int kc = 0; kc < 32; ++kc) {
            float4 w4 = *(const float4*)&Wc[kc * 1536 + g * 4];
#pragma unroll
            for (int j = 0; j < 4; ++j) {
                float wj = (j == 0) ? w4.x : (j == 1) ? w4.y : (j == 2) ? w4.z : w4.w;
                ull w2 = pk2(wj, wj);
                const ulonglong2* zp = (const ulonglong2*)&zs[(kc * 4 + j) * 16];
                ulonglong2 z0 = zp[0], z1 = zp[1], z2 = zp[2], z3 = zp[3];
                acc[0] = fma2(w2, z0.x, acc[0]);
                acc[1] = fma2(w2, z0.y, acc[1]);
                acc[2] = fma2(w2, z1.x, acc[2]);
                acc[3] = fma2(w2, z1.y, acc[3]);
                acc[4] = fma2(w2, z2.x, acc[4]);
                acc[5] = fma2(w2, z2.y, acc[5]);
                acc[6] = fma2(w2, z3.x, acc[6]);
                acc[7] = fma2(w2, z3.y, acc[7]);
            }
        }
        const int b = row0 >> 9, t0 = row0 & 511;     // 16 | 512 => tile never straddles b
        const size_t base = (size_t)t0 * ((size_t)BB * G3) + (size_t)b * G3 + g;
#pragma unroll
        for (int p = 0; p < 8; ++p) {
            float2 f = upk2(acc[p]);
            g_gx[base + (size_t)(2 * p) * (BB * G3)]     = f.x;
            g_gx[base + (size_t)(2 * p + 1) * (BB * G3)] = f.y;
        }
        __syncthreads();
    }
}

// ============================================================================
// Kernel B: sequential GRU scan. 128 CTAs x 4 batch rows, 384 threads
// (thread-per-gate). W_hh resident in SMEM for the whole T loop; gx streamed
// from HBM (prefetched at loop top). 2 __syncthreads per step.
// ============================================================================
__global__ void __launch_bounds__(384) k_gru(
    const float* __restrict__ hx, const int* __restrict__ done,
    const float* __restrict__ Whh, const float* __restrict__ bhh,
    const float* __restrict__ gr, const float* __restrict__ betar,
    const float* __restrict__ Wpol, const float* __restrict__ bpol,
    const float* __restrict__ Wval, const float* __restrict__ bval,
    float* __restrict__ out)
{
    extern __shared__ float sm[];
    float* Wc = sm;             // 49152 (chunked transposed W_hh)
    float* bh = Wc + 49152;     // 384
    float* hs = bh + 384;       // [k][4] carry h
    float* Hn = hs + 512;       // [k][4] h_new (pre-mask, for LN)
    float* Rs = Hn + 512;       // [k][4] r gate
    float* Us = Rs + 512;       // [k][4] u gate
    float* D1 = Us + 512;       // [r][512] (1 - done)
    float* Pr = D1 + 2048;      // float2[16]: [warp 0..3][row] (sum, sumsq)
    float* Gr = Pr + 32;        // 128
    float* Br = Gr + 128;       // 128
    float* Wp = Br + 128;       // [8][128]
    float* bp = Wp + 1024;      // 8
    float* Wv = bp + 8;         // 128
    float* bv = Wv + 128;       // 1 (+pad)

    const int tid = threadIdx.x, g = tid;
    const int lane = tid & 31, wid = tid >> 5;
    const int b0 = blockIdx.x * 4;

    for (int i = tid; i < 49152; i += 384) {
        int gg2 = i >> 7, k = i & 127;
        Wc[(k >> 2) * 1536 + gg2 * 4 + (k & 3)] = Whh[i];
    }
    bh[tid] = bhh[tid];
    for (int i = tid; i < 512; i += 384) {
        int r = i >> 7, k = i & 127;
        hs[k * 4 + r] = hx[(size_t)(b0 + r) * 128 + k];
    }
    for (int i = tid; i < 2048; i += 384) {
        int r = i >> 9, t = i & 511;
        D1[i] = 1.0f - (float)done[(size_t)(b0 + r) * 512 + t];
    }
    if (tid < 128) { Gr[tid] = gr[tid]; Br[tid] = betar[tid]; Wv[tid] = Wval[tid]; }
    for (int i = tid; i < 1024; i += 384) Wp[i] = Wpol[i];
    if (tid < 8) bp[tid] = bpol[tid];
    if (tid == 0) bv[0] = bval[0];
    __syncthreads();

    const float bhg = bh[g];
    const int kk = g - 256;    // k index for n-gate threads (g>=256)
    float hcar0 = 0.f, hcar1 = 0.f, hcar2 = 0.f, hcar3 = 0.f;

    for (int t = 0; t < 512; ++t) {
        // Prefetch gx for this step (latency hides under the k-loop)
        const float* gxp = g_gx + (size_t)t * (BB * G3) + (size_t)b0 * G3 + g;
        const float gx0 = gxp[0], gx1 = gxp[384], gx2 = gxp[768], gx3 = gxp[1152];

        // ---- P1: gh = W_hh @ h + b_hh (f32x2 over row pairs, 2 chains/pair)
        ull a01a = pk2(bhg, bhg), a01b = 0ULL;
        ull a23a = 0ULL,          a23b = 0ULL;
#pragma unroll
        for (int kc = 0; kc < 32; ++kc) {
            float4 w4 = *(const float4*)&Wc[kc * 1536 + g * 4];
#pragma unroll
            for (int j = 0; j < 4; ++j) {
                float wj = (j == 0) ? w4.x : (j == 1) ? w4.y : (j == 2) ? w4.z : w4.w;
                ull w2 = pk2(wj, wj);
                ulonglong2 hv = *(const ulonglong2*)&hs[(kc * 4 + j) * 4];
                if (j & 1) { a01b = fma2(w2, hv.x, a01b); a23b = fma2(w2, hv.y, a23b); }
                else       { a01a = fma2(w2, hv.x, a01a); a23a = fma2(w2, hv.y, a23a); }
            }
        }
        float2 f01a = upk2(a01a), f01b = upk2(a01b), f23a = upk2(a23a), f23b = upk2(a23b);
        const float gh0 = f01a.x + f01b.x, gh1 = f01a.y + f01b.y;
        const float gh2 = f23a.x + f23b.x, gh3 = f23a.y + f23b.y;

        // ---- P2: r / u gates (g<256); n-threads keep (gx, gh) split
        if (g < 128) {
            Rs[g * 4 + 0] = sigmf(gx0 + gh0);
            Rs[g * 4 + 1] = sigmf(gx1 + gh1);
            Rs[g * 4 + 2] = sigmf(gx2 + gh2);
            Rs[g * 4 + 3] = sigmf(gx3 + gh3);
        } else if (g < 256) {
            const int q = g - 128;
            Us[q * 4 + 0] = sigmf(gx0 + gh0);
            Us[q * 4 + 1] = sigmf(gx1 + gh1);
            Us[q * 4 + 2] = sigmf(gx2 + gh2);
            Us[q * 4 + 3] = sigmf(gx3 + gh3);
        }
        __syncthreads();   // SYNC_A

        // ---- P3: n gate, h update, per-warp LN partials (warps 8..11)
        if (g >= 256) {
            float s0, s1, s2, s3, q0, q1, q2, q3;
            {
                const float u = Us[kk * 4 + 0];
                const float n = tanhf(gx0 + Rs[kk * 4 + 0] * gh0);
                const float hvv = (1.f - u) * n + u * hs[kk * 4 + 0];
                Hn[kk * 4 + 0] = hvv; hcar0 = hvv * D1[t];
                hs[kk * 4 + 0] = hcar0; s0 = hvv; q0 = hvv * hvv;
            }
            {
                const float u = Us[kk * 4 + 1];
                const float n = tanhf(gx1 + Rs[kk * 4 + 1] * gh1);
                const float hvv = (1.f - u) * n + u * hs[kk * 4 + 1];
                Hn[kk * 4 + 1] = hvv; hcar1 = hvv * D1[512 + t];
                hs[kk * 4 + 1] = hcar1; s1 = hvv; q1 = hvv * hvv;
            }
            {
                const float u = Us[kk * 4 + 2];
                const float n = tanhf(gx2 + Rs[kk * 4 + 2] * gh2);
                const float hvv = (1.f - u) * n + u * hs[kk * 4 + 2];
                Hn[kk * 4 + 2] = hvv; hcar2 = hvv * D1[1024 + t];
                hs[kk * 4 + 2] = hcar2; s2 = hvv; q2 = hvv * hvv;
            }
            {
                const float u = Us[kk * 4 + 3];
                const float n = tanhf(gx3 + Rs[kk * 4 + 3] * gh3);
                const float hvv = (1.f - u) * n + u * hs[kk * 4 + 3];
                Hn[kk * 4 + 3] = hvv; hcar3 = hvv * D1[1536 + t];
                hs[kk * 4 + 3] = hcar3; s3 = hvv; q3 = hvv * hvv;
            }
#pragma unroll
            for (int o = 16; o > 0; o >>= 1) {
                s0 += __shfl_xor_sync(0xffffffffu, s0, o);
                s1 += __shfl_xor_sync(0xffffffffu, s1, o);
                s2 += __shfl_xor_sync(0xffffffffu, s2, o);
                s3 += __shfl_xor_sync(0xffffffffu, s3, o);
                q0 += __shfl_xor_sync(0xffffffffu, q0, o);
                q1 += __shfl_xor_sync(0xffffffffu, q1, o);
                q2 += __shfl_xor_sync(0xffffffffu, q2, o);
                q3 += __shfl_xor_sync(0xffffffffu, q3, o);
            }
            if (lane == 0) {
                float2* P2p = (float2*)Pr;
                const int wi = wid - 8;
                P2p[wi * 4 + 0] = make_float2(s0, q0);
                P2p[wi * 4 + 1] = make_float2(s1, q1);
                P2p[wi * 4 + 2] = make_float2(s2, q2);
                P2p[wi * 4 + 3] = make_float2(s3, q3);
            }
        }
        __syncthreads();   // SYNC_B

        // ---- P4: LN(y) + policy/value heads. 12 warps x 3 dots = 36 dots
        {
            const float2* P2p = (const float2*)Pr;
#pragma unroll
            for (int j = 0; j < 3; ++j) {
                const int d = wid * 3 + j;
                const int row = d / 9, o = d - row * 9;
                float2 p0 = P2p[row], p1 = P2p[4 + row], p2 = P2p[8 + row], p3 = P2p[12 + row];
                const float sum = p0.x + p1.x + p2.x + p3.x;
                const float sq  = p0.y + p1.y + p2.y + p3.y;
                const float mu = sum * (1.f / 128.f);
                const float rstd = rsqrtf(sq * (1.f / 128.f) - mu * mu + 1e-5f);
                const float* wsel = (o < 8) ? (Wp + o * 128) : Wv;
                float accd = 0.f;
#pragma unroll
                for (int q4 = 0; q4 < 4; ++q4) {
                    const int k = lane + 32 * q4;
                    const float y = (Hn[k * 4 + row] - mu) * rstd * Gr[k] + Br[k];
                    accd += y * wsel[k];
                }
#pragma unroll
                for (int o2 = 16; o2 > 0; o2 >>= 1)
                    accd += __shfl_xor_sync(0xffffffffu, accd, o2);
                if (lane == 0) {
                    if (o < 8)
                        out[(size_t)(b0 + row) * 4096 + (size_t)t * 8 + o] = accd + bp[o];
                    else
                        out[2097152u + (size_t)(b0 + row) * 512 + t] = accd + bv[0];
                }
            }
        }
    }

    // h_fin (masked carry after t=511), straight from the n-threads' registers
    if (g >= 256) {
        out[2359296u + (size_t)(b0 + 0) * 128 + kk] = hcar0;
        out[2359296u + (size_t)(b0 + 1) * 128 + kk] = hcar1;
        out[2359296u + (size_t)(b0 + 2) * 128 + kk] = hcar2;
        out[2359296u + (size_t)(b0 + 3) * 128 + kk] = hcar3;
    }
}

// ============================================================================
extern "C" void kernel_launch(void* const* d_in, const int* in_sizes, int n_in,
                              void* d_out, int out_size)
{
    const float* x     = (const float*)d_in[0];
    const float* hx    = (const float*)d_in[1];
    const int*   done  = (const int*)d_in[2];
    const float* Wf    = (const float*)d_in[3];
    const float* bf    = (const float*)d_in[4];
    const float* gf    = (const float*)d_in[5];
    const float* betaf = (const float*)d_in[6];
    const float* Wih   = (const float*)d_in[7];
    const float* Whh   = (const float*)d_in[8];
    const float* bih   = (const float*)d_in[9];
    const float* bhh   = (const float*)d_in[10];
    const float* gr    = (const float*)d_in[11];
    const float* betar = (const float*)d_in[12];
    const float* Wpol  = (const float*)d_in[13];
    const float* bpol  = (const float*)d_in[14];
    const float* Wval  = (const float*)d_in[15];
    const float* bval  = (const float*)d_in[16];
    float* out = (float*)d_out;

    const size_t smA1 = (8192 + 1024 + 2048 + 384) * sizeof(float);                 // ~46.6 KB
    const size_t smA2 = (49152 + 2048 + 384) * sizeof(float);                        // ~206 KB
    const size_t smB  = (49152 + 384 + 512 * 4 + 2048 + 32 + 128 + 128 + 1024 + 8
                         + 128 + 4) * sizeof(float);                                 // ~220 KB

    cudaFuncSetAttribute(k_feat, cudaFuncAttributeMaxDynamicSharedMemorySize, (int)smA1);
    cudaFuncSetAttribute(k_gx,   cudaFuncAttributeMaxDynamicSharedMemorySize, (int)smA2);
    cudaFuncSetAttribute(k_gru,  cudaFuncAttributeMaxDynamicSharedMemorySize, (int)smB);

    k_feat<<<592, 256, smA1>>>(x, Wf, bf, gf, betaf);
    k_gx<<<148, 384, smA2>>>(Wih, bih);
    k_gru<<<128, 384, smB>>>(hx, done, Whh, bhh, gr, betar, Wpol, bpol, Wval, bval, out);
}

// round 4
// speedup vs baseline: 1.1174x; 1.1174x over previous
#include <cuda_runtime.h>
#include <cstdint>

#define BB 512
#define TT 512
#define SS 64
#define HH 128
#define G3 384
#define AA 8

__device__ float g_z[(size_t)BB * TT * HH];   // 134 MB
__device__ float g_gx[(size_t)BB * TT * G3];  // 402 MB, layout (T,B,3H)

typedef unsigned long long ull;

__device__ __forceinline__ ull pk2(float lo, float hi) {
    ull r; asm("mov.b64 %0, {%1,%2};" : "=l"(r) : "f"(lo), "f"(hi)); return r;
}
__device__ __forceinline__ float2 upk2(ull v) {
    float2 f; asm("mov.b64 {%0,%1}, %2;" : "=f"(f.x), "=f"(f.y) : "l"(v)); return f;
}
__device__ __forceinline__ ull fma2(ull a, ull b, ull c) {
    ull d; asm("fma.rn.f32x2 %0, %1, %2, %3;" : "=l"(d) : "l"(a), "l"(b), "l"(c)); return d;
}
__device__ __forceinline__ float sigmf(float x) { return 1.0f / (1.0f + __expf(-x)); }

// ============================================================================
// A1: z = relu(LN(x @ Wf^T + bf)). Weights in registers, broadcast LDS x-tile.
// ============================================================================
__global__ void __launch_bounds__(256) k_feat(
    const float* __restrict__ x, const float* __restrict__ Wf,
    const float* __restrict__ bf, const float* __restrict__ gf,
    const float* __restrict__ betaf)
{
    __shared__ __align__(16) float xs2[1024];
    __shared__ float fs[2048];
    __shared__ float gfs[128], bes[128];

    const int tid = threadIdx.x, h = tid & 127, gg = tid >> 7;
    const int lane = tid & 31, wid = tid >> 5;

    ull wreg[32];
#pragma unroll
    for (int i = 0; i < 32; ++i) {
        float2 wf = *(const float2*)(Wf + (size_t)h * 64 + 2 * i);
        wreg[i] = pk2(wf.x, wf.y);
    }
    if (tid < 128) { gfs[tid] = gf[tid]; bes[tid] = betaf[tid]; }
    const float bbv = bf[h];

    for (int tile = blockIdx.x; tile < (BB * TT / 16); tile += gridDim.x) {
        const int row0 = tile * 16;
        __syncthreads();
        for (int i = tid; i < 1024; i += 256) {
            int r = i >> 6, s = i & 63;
            xs2[(s >> 1) * 32 + r * 2 + (s & 1)] = x[(size_t)(row0 + r) * 64 + s];
        }
        __syncthreads();

        ull a[8];
#pragma unroll
        for (int p = 0; p < 8; ++p) a[p] = 0ULL;
#pragma unroll
        for (int i = 0; i < 32; ++i) {
            const float* bp2 = xs2 + i * 32 + gg * 16;
            ulonglong2 u01 = *(const ulonglong2*)(bp2);
            ulonglong2 u23 = *(const ulonglong2*)(bp2 + 4);
            ulonglong2 u45 = *(const ulonglong2*)(bp2 + 8);
            ulonglong2 u67 = *(const ulonglong2*)(bp2 + 12);
            a[0] = fma2(wreg[i], u01.x, a[0]); a[1] = fma2(wreg[i], u01.y, a[1]);
            a[2] = fma2(wreg[i], u23.x, a[2]); a[3] = fma2(wreg[i], u23.y, a[3]);
            a[4] = fma2(wreg[i], u45.x, a[4]); a[5] = fma2(wreg[i], u45.y, a[5]);
            a[6] = fma2(wreg[i], u67.x, a[6]); a[7] = fma2(wreg[i], u67.y, a[7]);
        }
#pragma unroll
        for (int p = 0; p < 8; ++p) {
            float2 f = upk2(a[p]);
            fs[(gg * 8 + p) * 128 + h] = f.x + f.y + bbv;
        }
        __syncthreads();

#pragma unroll
        for (int rr = 0; rr < 2; ++rr) {
            const int row = wid * 2 + rr;
            float v[4], s1 = 0.f, s2 = 0.f;
#pragma unroll
            for (int q = 0; q < 4; ++q) {
                v[q] = fs[row * 128 + lane + 32 * q];
                s1 += v[q]; s2 += v[q] * v[q];
            }
#pragma unroll
            for (int o = 16; o > 0; o >>= 1) {
                s1 += __shfl_xor_sync(0xffffffffu, s1, o);
                s2 += __shfl_xor_sync(0xffffffffu, s2, o);
            }
            const float mu = s1 * (1.f / 128.f);
            const float rstd = rsqrtf(s2 * (1.f / 128.f) - mu * mu + 1e-5f);
#pragma unroll
            for (int q = 0; q < 4; ++q) {
                int k = lane + 32 * q;
                float zv = (v[q] - mu) * rstd * gfs[k] + bes[k];
                g_z[(size_t)(row0 + row) * 128 + k] = fmaxf(zv, 0.f);
            }
        }
    }
}

// ============================================================================
// A2: gx = z @ Wih^T + bih -> (T,B,3H). Weights in registers, 8-row tiles.
// ============================================================================
__global__ void __launch_bounds__(384) k_gx(
    const float* __restrict__ Wih, const float* __restrict__ bih)
{
    __shared__ __align__(16) float zs2[1024];

    const int tid = threadIdx.x, g = tid;
    ull wreg[64];
#pragma unroll
    for (int i = 0; i < 64; ++i) {
        float2 wf = *(const float2*)(Wih + (size_t)g * 128 + 2 * i);
        wreg[i] = pk2(wf.x, wf.y);
    }
    const float bbv = bih[g];

    for (int tile = blockIdx.x; tile < (BB * TT / 8); tile += gridDim.x) {
        const int row0 = tile * 8;
        __syncthreads();
        for (int i = tid; i < 1024; i += 384) {
            int r = i >> 7, k = i & 127;
            zs2[(k >> 1) * 16 + r * 2 + (k & 1)] = g_z[(size_t)(row0 + r) * 128 + k];
        }
        __syncthreads();

        ull a[8];
#pragma unroll
        for (int p = 0; p < 8; ++p) a[p] = 0ULL;
#pragma unroll
        for (int i = 0; i < 64; ++i) {
            const float* bp2 = zs2 + i * 16;
            ulonglong2 u01 = *(const ulonglong2*)(bp2);
            ulonglong2 u23 = *(const ulonglong2*)(bp2 + 4);
            ulonglong2 u45 = *(const ulonglong2*)(bp2 + 8);
            ulonglong2 u67 = *(const ulonglong2*)(bp2 + 12);
            a[0] = fma2(wreg[i], u01.x, a[0]); a[1] = fma2(wreg[i], u01.y, a[1]);
            a[2] = fma2(wreg[i], u23.x, a[2]); a[3] = fma2(wreg[i], u23.y, a[3]);
            a[4] = fma2(wreg[i], u45.x, a[4]); a[5] = fma2(wreg[i], u45.y, a[5]);
            a[6] = fma2(wreg[i], u67.x, a[6]); a[7] = fma2(wreg[i], u67.y, a[7]);
        }
        const int b = row0 >> 9, t0 = row0 & 511;
        const size_t base = (size_t)t0 * ((size_t)BB * G3) + (size_t)b * G3 + g;
#pragma unroll
        for (int p = 0; p < 8; ++p) {
            float2 f = upk2(a[p]);
            g_gx[base + (size_t)p * (BB * G3)] = f.x + f.y + bbv;
        }
    }
}

// ============================================================================
// B: sequential GRU scan. W_hh register-resident; broadcast LDS h; 2 bars/step.
// ============================================================================
__global__ void __launch_bounds__(384) k_gru(
    const float* __restrict__ hx, const int* __restrict__ done,
    const float* __restrict__ Whh, const float* __restrict__ bhh,
    const float* __restrict__ gr, const float* __restrict__ betar,
    const float* __restrict__ Wpol, const float* __restrict__ bpol,
    const float* __restrict__ Wval, const float* __restrict__ bval,
    float* __restrict__ out)
{
    __shared__ __align__(16) float hs2[512];
    __shared__ float Hn[512];
    __shared__ float Rs[512];
    __shared__ float Us[512];
    __shared__ float D1[2048];
    __shared__ float2 Pr[16];
    __shared__ float Gr[128], Br[128], Wp[1024], bp[8], Wv[128], bv[1];

    const int tid = threadIdx.x, g = tid;
    const int lane = tid & 31, wid = tid >> 5;
    const int b0 = blockIdx.x * 4;

    ull wreg[64];
#pragma unroll
    for (int i = 0; i < 64; ++i) {
        float2 wf = *(const float2*)(Whh + (size_t)g * 128 + 2 * i);
        wreg[i] = pk2(wf.x, wf.y);
    }
    const float bhg = bhh[g];

    for (int i = tid; i < 512; i += 384) {
        int r = i >> 7, k = i & 127;
        hs2[(k >> 1) * 8 + r * 2 + (k & 1)] = hx[(size_t)(b0 + r) * 128 + k];
    }
    for (int i = tid; i < 2048; i += 384) {
        int r = i >> 9, t = i & 511;
        D1[i] = 1.0f - (float)done[(size_t)(b0 + r) * 512 + t];
    }
    if (tid < 128) { Gr[tid] = gr[tid]; Br[tid] = betar[tid]; Wv[tid] = Wval[tid]; }
    for (int i = tid; i < 1024; i += 384) Wp[i] = Wpol[i];
    if (tid < 8) bp[tid] = bpol[tid];
    if (tid == 0) bv[0] = bval[0];
    __syncthreads();

    const int kk = g & 127;
    float hcar0 = 0.f, hcar1 = 0.f, hcar2 = 0.f, hcar3 = 0.f;

    for (int t = 0; t < 512; ++t) {
        const float* gxp = g_gx + (size_t)t * (BB * G3) + (size_t)b0 * G3 + g;
        const float gx0 = gxp[0], gx1 = gxp[384], gx2 = gxp[768], gx3 = gxp[1152];

        // P1: gh = W_hh @ h + b_hh
        ull a0 = 0ULL, a1 = 0ULL, a2 = 0ULL, a3 = 0ULL;
#pragma unroll
        for (int i = 0; i < 64; ++i) {
            ulonglong2 u01 = *(const ulonglong2*)(hs2 + i * 8);
            ulonglong2 u23 = *(const ulonglong2*)(hs2 + i * 8 + 4);
            a0 = fma2(wreg[i], u01.x, a0);
            a1 = fma2(wreg[i], u01.y, a1);
            a2 = fma2(wreg[i], u23.x, a2);
            a3 = fma2(wreg[i], u23.y, a3);
        }
        float2 f0 = upk2(a0), f1 = upk2(a1), f2 = upk2(a2), f3 = upk2(a3);
        const float gh0 = f0.x + f0.y + bhg, gh1 = f1.x + f1.y + bhg;
        const float gh2 = f2.x + f2.y + bhg, gh3 = f3.x + f3.y + bhg;

        // P2: r / u gates
        if (g < 128) {
            Rs[g * 4 + 0] = sigmf(gx0 + gh0);
            Rs[g * 4 + 1] = sigmf(gx1 + gh1);
            Rs[g * 4 + 2] = sigmf(gx2 + gh2);
            Rs[g * 4 + 3] = sigmf(gx3 + gh3);
        } else if (g < 256) {
            const int q = g & 127;
            Us[q * 4 + 0] = sigmf(gx0 + gh0);
            Us[q * 4 + 1] = sigmf(gx1 + gh1);
            Us[q * 4 + 2] = sigmf(gx2 + gh2);
            Us[q * 4 + 3] = sigmf(gx3 + gh3);
        }
        __syncthreads();   // SYNC_A

        // P3: n gate, h update, LN partials (warps 8..11)
        if (g >= 256) {
            const int hb = (kk >> 1) * 8 + (kk & 1);
            float s0, s1, s2, s3, q0, q1, q2, q3;
            {
                const float hprev = hs2[hb + 0];
                const float u = Us[kk * 4 + 0];
                const float n = tanhf(gx0 + Rs[kk * 4 + 0] * gh0);
                const float hvv = (1.f - u) * n + u * hprev;
                Hn[kk * 4 + 0] = hvv; hcar0 = hvv * D1[t];
                hs2[hb + 0] = hcar0; s0 = hvv; q0 = hvv * hvv;
            }
            {
                const float hprev = hs2[hb + 2];
                const float u = Us[kk * 4 + 1];
                const float n = tanhf(gx1 + Rs[kk * 4 + 1] * gh1);
                const float hvv = (1.f - u) * n + u * hprev;
                Hn[kk * 4 + 1] = hvv; hcar1 = hvv * D1[512 + t];
                hs2[hb + 2] = hcar1; s1 = hvv; q1 = hvv * hvv;
            }
            {
                const float hprev = hs2[hb + 4];
                const float u = Us[kk * 4 + 2];
                const float n = tanhf(gx2 + Rs[kk * 4 + 2] * gh2);
                const float hvv = (1.f - u) * n + u * hprev;
                Hn[kk * 4 + 2] = hvv; hcar2 = hvv * D1[1024 + t];
                hs2[hb + 4] = hcar2; s2 = hvv; q2 = hvv * hvv;
            }
            {
                const float hprev = hs2[hb + 6];
                const float u = Us[kk * 4 + 3];
                const float n = tanhf(gx3 + Rs[kk * 4 + 3] * gh3);
                const float hvv = (1.f - u) * n + u * hprev;
                Hn[kk * 4 + 3] = hvv; hcar3 = hvv * D1[1536 + t];
                hs2[hb + 6] = hcar3; s3 = hvv; q3 = hvv * hvv;
            }
#pragma unroll
            for (int o = 16; o > 0; o >>= 1) {
                s0 += __shfl_xor_sync(0xffffffffu, s0, o);
                s1 += __shfl_xor_sync(0xffffffffu, s1, o);
                s2 += __shfl_xor_sync(0xffffffffu, s2, o);
                s3 += __shfl_xor_sync(0xffffffffu, s3, o);
                q0 += __shfl_xor_sync(0xffffffffu, q0, o);
                q1 += __shfl_xor_sync(0xffffffffu, q1, o);
                q2 += __shfl_xor_sync(0xffffffffu, q2, o);
                q3 += __shfl_xor_sync(0xffffffffu, q3, o);
            }
            if (lane == 0) {
                const int wi = wid - 8;
                Pr[wi * 4 + 0] = make_float2(s0, q0);
                Pr[wi * 4 + 1] = make_float2(s1, q1);
                Pr[wi * 4 + 2] = make_float2(s2, q2);
                Pr[wi * 4 + 3] = make_float2(s3, q3);
            }
        }
        __syncthreads();   // SYNC_B

        // P4: LN(y) + heads
        {
#pragma unroll
            for (int j = 0; j < 3; ++j) {
                const int d = wid * 3 + j;
                const int row = d / 9, o = d - row * 9;
                float2 p0 = Pr[row], p1 = Pr[4 + row], p2 = Pr[8 + row], p3 = Pr[12 + row];
                const float sum = p0.x + p1.x + p2.x + p3.x;
                const float sq  = p0.y + p1.y + p2.y + p3.y;
                const float mu = sum * (1.f / 128.f);
                const float rstd = rsqrtf(sq * (1.f / 128.f) - mu * mu + 1e-5f);
                const float* wsel = (o < 8) ? (Wp + o * 128) : Wv;
                float accd = 0.f;
#pragma unroll
                for (int q4 = 0; q4 < 4; ++q4) {
                    const int k = lane + 32 * q4;
                    const float y = (Hn[k * 4 + row] - mu) * rstd * Gr[k] + Br[k];
                    accd += y * wsel[k];
                }
#pragma unroll
                for (int o2 = 16; o2 > 0; o2 >>= 1)
                    accd += __shfl_xor_sync(0xffffffffu, accd, o2);
                if (lane == 0) {
                    if (o < 8)
                        out[(size_t)(b0 + row) * 4096 + (size_t)t * 8 + o] = accd + bp[o];
                    else
                        out[2097152u + (size_t)(b0 + row) * 512 + t] = accd + bv[0];
                }
            }
        }
    }

    if (g >= 256) {
        out[2359296u + (size_t)(b0 + 0) * 128 + kk] = hcar0;
        out[2359296u + (size_t)(b0 + 1) * 128 + kk] = hcar1;
        out[2359296u + (size_t)(b0 + 2) * 128 + kk] = hcar2;
        out[2359296u + (size_t)(b0 + 3) * 128 + kk] = hcar3;
    }
}

extern "C" void kernel_launch(void* const* d_in, const int* in_sizes, int n_in,
                              void* d_out, int out_size)
{
    const float* x     = (const float*)d_in[0];
    const float* hx    = (const float*)d_in[1];
    const int*   done  = (const int*)d_in[2];
    const float* Wf    = (const float*)d_in[3];
    const float* bf    = (const float*)d_in[4];
    const float* gf    = (const float*)d_in[5];
    const float* betaf = (const float*)d_in[6];
    const float* Wih   = (const float*)d_in[7];
    const float* Whh   = (const float*)d_in[8];
    const float* bih   = (const float*)d_in[9];
    const float* bhh   = (const float*)d_in[10];
    const float* gr    = (const float*)d_in[11];
    const float* betar = (const float*)d_in[12];
    const float* Wpol  = (const float*)d_in[13];
    const float* bpol  = (const float*)d_in[14];
    const float* Wval  = (const float*)d_in[15];
    const float* bval  = (const float*)d_in[16];
    float* out = (float*)d_out;

    k_feat<<<296, 256>>>(x, Wf, bf, gf, betaf);
    k_gx<<<148, 384>>>(Wih, bih);
    k_gru<<<128, 384>>>(hx, done, Whh, bhh, gr, betar, Wpol, bpol, Wval, bval, out);
}